// round 7
// baseline (speedup 1.0000x reference)
#include <cuda_runtime.h>
#include <math.h>

// Problem constants
constexpr int B = 8, T = 8, H = 14, W = 14;
constexpr int P = T * H * W;     // 1568
constexpr int N = B * P;         // 12544  (= 98*128, = 49*256)
constexpr float BN_EPS = 1e-5f;

// ---------------------------------------------------------------------------
// Scratch (no allocations allowed -> __device__ globals)
// ---------------------------------------------------------------------------
__device__ float g_samp[54190080];  // max Cin*K*N = 4320*12544 (layer2), reused as im2col
__device__ float g_off[1016064];    // max 3K*N = 81*12544
__device__ float g_outb[4014080];   // max Cout*N = 320*12544
__device__ float g_t1[2007040];     // branch1 mid act: B*160*P
__device__ float g_t3[401408];      // branch2 mid act: B*32*P
__device__ float g_xm[10436608];    // maxpool: B*832*P
__device__ float g_mean[320];
__device__ float g_var[320];

// ---------------------------------------------------------------------------
// im2col (k=3 layers only): COL[(c*K+tap)][n] = Xpad[b][c][...]
// ---------------------------------------------------------------------------
__global__ void im2col_k(const float* __restrict__ X, float* __restrict__ COL,
                         int Cin, int kc, int pad, int total) {
    int idx = blockIdx.x * blockDim.x + threadIdx.x;
    if (idx >= total) return;
    int n = idx % N;
    int ck = idx / N;
    int K = kc * kc * kc;
    int tap = ck % K;
    int c = ck / K;
    int b = n / P, p = n % P;
    int t = p / (H * W), h = (p / W) % H, w = p % W;
    int kt = tap / (kc * kc), kh = (tap / kc) % kc, kw = tap % kc;
    int tz = t - pad + kt, hy = h - pad + kh, wx = w - pad + kw;
    float v = 0.f;
    if (tz >= 0 && tz < T && hy >= 0 && hy < H && wx >= 0 && wx < W)
        v = X[(size_t)(b * Cin + c) * P + (tz * H + hy) * W + wx];
    COL[idx] = v;
}

// ---------------------------------------------------------------------------
// SGEMM 128x128, BK=8, 256 threads, 8x8 microtile, double-buffered smem.
// C[M][N] = A[M][Kd] * Bm[Kd][N] (+bias). Requires Kd%8==0, N%128==0.
// ---------------------------------------------------------------------------
__global__ __launch_bounds__(256) void sgemm128_k(
    const float* __restrict__ A, const float* __restrict__ Bm,
    const float* __restrict__ bias, float* __restrict__ C, int M, int Kd) {
    __shared__ float As[2][8][128];
    __shared__ float Bs[2][8][128];

    int tid = threadIdx.x;
    int bm = blockIdx.y * 128, bn = blockIdx.x * 128;

    int aRow = tid >> 1, aK = (tid & 1) * 4;    // A tile: 128 m x 8 k
    int bK = tid >> 5, bN = (tid & 31) * 4;     // B tile: 8 k x 128 n
    int ty = tid >> 4, tx = tid & 15;           // 8x8 out: m=bm+ty*8+i, n=bn+tx*8+j

    bool aval = (bm + aRow) < M;
    const float* Aptr = A + (size_t)(bm + aRow) * Kd + aK;
    const float* Bptr = Bm + (size_t)bK * N + bn + bN;

    float4 a4 = aval ? *(const float4*)Aptr : make_float4(0.f, 0.f, 0.f, 0.f);
    float4 b4 = *(const float4*)Bptr;
    As[0][aK + 0][aRow] = a4.x; As[0][aK + 1][aRow] = a4.y;
    As[0][aK + 2][aRow] = a4.z; As[0][aK + 3][aRow] = a4.w;
    *(float4*)&Bs[0][bK][bN] = b4;
    __syncthreads();

    float acc[8][8] = {};
    int KT = Kd / 8;
    for (int kt = 0; kt < KT; kt++) {
        int buf = kt & 1;
        if (kt + 1 < KT) {
            a4 = aval ? *(const float4*)(Aptr + (kt + 1) * 8)
                      : make_float4(0.f, 0.f, 0.f, 0.f);
            b4 = *(const float4*)(Bptr + (size_t)(kt + 1) * 8 * N);
        }
#pragma unroll
        for (int kk = 0; kk < 8; kk++) {
            float af[8], bf[8];
            *(float4*)(af)     = *(float4*)&As[buf][kk][ty * 8];
            *(float4*)(af + 4) = *(float4*)&As[buf][kk][ty * 8 + 4];
            *(float4*)(bf)     = *(float4*)&Bs[buf][kk][tx * 8];
            *(float4*)(bf + 4) = *(float4*)&Bs[buf][kk][tx * 8 + 4];
#pragma unroll
            for (int i = 0; i < 8; i++) {
#pragma unroll
                for (int j = 0; j < 8; j++)
                    acc[i][j] = fmaf(af[i], bf[j], acc[i][j]);
            }
        }
        if (kt + 1 < KT) {
            int nb = buf ^ 1;
            As[nb][aK + 0][aRow] = a4.x; As[nb][aK + 1][aRow] = a4.y;
            As[nb][aK + 2][aRow] = a4.z; As[nb][aK + 3][aRow] = a4.w;
            *(float4*)&Bs[nb][bK][bN] = b4;
            __syncthreads();
        }
    }

#pragma unroll
    for (int i = 0; i < 8; i++) {
        int m = bm + ty * 8 + i;
        if (m >= M) continue;
        float bv = bias ? bias[m] : 0.f;
        float4 o0 = make_float4(acc[i][0] + bv, acc[i][1] + bv,
                                acc[i][2] + bv, acc[i][3] + bv);
        float4 o1 = make_float4(acc[i][4] + bv, acc[i][5] + bv,
                                acc[i][6] + bv, acc[i][7] + bv);
        float* cp = &C[(size_t)m * N + bn + tx * 8];
        *(float4*)cp = o0;
        *(float4*)(cp + 4) = o1;
    }
}

// ---------------------------------------------------------------------------
// gemv3: OFF[3][N] = woff[3][Cin] @ X (native [B][Cin][P]) + boff.
// One thread per n; W staged in smem. Replaces im2col+GEMM for k=1 offsets.
// ---------------------------------------------------------------------------
__global__ __launch_bounds__(256) void gemv3_k(
    const float* __restrict__ W, const float* __restrict__ bias,
    const float* __restrict__ X, float* __restrict__ OUT, int Cin) {
    __shared__ float ws[3 * 832];
    int tid = threadIdx.x;
    for (int i = tid; i < 3 * Cin; i += 256) ws[i] = W[i];
    __syncthreads();
    int n = blockIdx.x * 256 + tid;  // grid = 49, exact
    int b = n / P, p = n % P;
    const float* xp = X + (size_t)b * Cin * P + p;
    float a0 = bias[0], a1 = bias[1], a2 = bias[2];
#pragma unroll 4
    for (int c = 0; c < Cin; c++) {
        float xv = xp[(size_t)c * P];
        a0 = fmaf(xv, ws[c], a0);
        a1 = fmaf(xv, ws[Cin + c], a1);
        a2 = fmaf(xv, ws[2 * Cin + c], a2);
    }
    OUT[n] = a0;
    OUT[N + n] = a1;
    OUT[2 * N + n] = a2;
}

// ---------------------------------------------------------------------------
// gemv32: C[32][N] = W[32][Kd] @ Bm[Kd][N]. 2 columns per thread.
// ---------------------------------------------------------------------------
__global__ __launch_bounds__(256) void gemv32_k(
    const float* __restrict__ W, const float* __restrict__ Bm,
    float* __restrict__ C, int Kd) {
    __shared__ float ws[32][64];
    int tid = threadIdx.x;
    int n0 = blockIdx.x * 512 + tid;
    int n1 = n0 + 256;
    bool v1 = n1 < N;
    float acc0[32] = {}, acc1[32] = {};
    for (int c0 = 0; c0 < Kd; c0 += 64) {
        __syncthreads();
        for (int i = tid; i < 2048; i += 256) {
            int o = i >> 6, c = i & 63;
            ws[o][c] = W[(size_t)o * Kd + c0 + c];
        }
        __syncthreads();
#pragma unroll 4
        for (int c = 0; c < 64; c++) {
            const float* bp = Bm + (size_t)(c0 + c) * N;
            float x0 = bp[n0];
            float x1 = v1 ? bp[n1] : 0.f;
#pragma unroll
            for (int o = 0; o < 32; o++) {
                float wv = ws[o][c];
                acc0[o] = fmaf(x0, wv, acc0[o]);
                acc1[o] = fmaf(x1, wv, acc1[o]);
            }
        }
    }
    for (int o = 0; o < 32; o++) {
        C[(size_t)o * N + n0] = acc0[o];
        if (v1) C[(size_t)o * N + n1] = acc1[o];
    }
}

// ---------------------------------------------------------------------------
// Deformable trilinear sampling. OFF [3K][N]; SAMP[(c*K+k)][n].
// ---------------------------------------------------------------------------
__global__ __launch_bounds__(128) void dsample_k(
    const float* __restrict__ X, const float* __restrict__ OFF,
    float* __restrict__ SAMP, int Cin, int kc, int pad) {
    int n = blockIdx.x * blockDim.x + threadIdx.x;
    int k = blockIdx.y;
    int K = kc * kc * kc;
    int b = n / P, p = n % P;
    int t = p / (H * W), h = (p / W) % H, w = p % W;
    int kt = k / (kc * kc), kh = (k / kc) % kc, kw = k % kc;

    float tc = (float)(t - pad + kt) + OFF[(size_t)(k * 3 + 0) * N + n];
    float hc = (float)(h - pad + kh) + OFF[(size_t)(k * 3 + 1) * N + n];
    float wc = (float)(w - pad + kw) + OFF[(size_t)(k * 3 + 2) * N + n];
    float t0 = floorf(tc), h0 = floorf(hc), w0 = floorf(wc);

    int lin[8];
    float wg[8];
#pragma unroll
    for (int d = 0; d < 8; d++) {
        float ti = t0 + (float)(d >> 2);
        float hi = h0 + (float)((d >> 1) & 1);
        float wi = w0 + (float)(d & 1);
        float wgt = (1.f - fabsf(tc - ti)) * (1.f - fabsf(hc - hi)) *
                    (1.f - fabsf(wc - wi));
        bool valid = (ti >= 0.f) && (ti < (float)T) && (hi >= 0.f) &&
                     (hi < (float)H) && (wi >= 0.f) && (wi < (float)W);
        wg[d] = valid ? wgt : 0.f;
        int it = min(max((int)ti, 0), T - 1);
        int ih = min(max((int)hi, 0), H - 1);
        int iw = min(max((int)wi, 0), W - 1);
        lin[d] = (it * H + ih) * W + iw;
    }

    const float* xb = X + (size_t)b * Cin * P;
    float* sp = SAMP + (size_t)k * N + n;
    size_t cstride = (size_t)K * N;
#pragma unroll 2
    for (int c = 0; c < Cin; c++) {
        const float* xc = xb + (size_t)c * P;
        float v = 0.f;
#pragma unroll
        for (int d = 0; d < 8; d++) v = fmaf(wg[d], xc[lin[d]], v);
        sp[(size_t)c * cstride] = v;
    }
}

// ---------------------------------------------------------------------------
// MaxPool3d 3x3x3 stride 1 pad 1 over [B*C][P]
// ---------------------------------------------------------------------------
__global__ void maxpool_k(const float* __restrict__ X, float* __restrict__ Y,
                          int totBC) {
    int idx = blockIdx.x * blockDim.x + threadIdx.x;
    if (idx >= totBC * P) return;
    int p = idx % P;
    int bc = idx / P;
    int t = p / (H * W), h = (p / W) % H, w = p % W;
    const float* xb = X + (size_t)bc * P;
    float m = -INFINITY;
    for (int dt = -1; dt <= 1; dt++) {
        int tz = t + dt;
        if (tz < 0 || tz >= T) continue;
        for (int dh = -1; dh <= 1; dh++) {
            int hy = h + dh;
            if (hy < 0 || hy >= H) continue;
            for (int dw = -1; dw <= 1; dw++) {
                int wx = w + dw;
                if (wx < 0 || wx >= W) continue;
                m = fmaxf(m, xb[(tz * H + hy) * W + wx]);
            }
        }
    }
    Y[idx] = m;
}

// ---------------------------------------------------------------------------
// BN batch stats per channel (biased var), one block per channel. float4 loads.
// ---------------------------------------------------------------------------
__global__ __launch_bounds__(256) void bnstats_k(const float* __restrict__ OUT,
                                                 float* __restrict__ mean,
                                                 float* __restrict__ var) {
    int o = blockIdx.x;
    const float4* row = (const float4*)(OUT + (size_t)o * N);
    float s = 0.f, sq = 0.f;
    for (int n = threadIdx.x; n < N / 4; n += blockDim.x) {
        float4 v = row[n];
        s += v.x + v.y + v.z + v.w;
        sq += v.x * v.x + v.y * v.y + v.z * v.z + v.w * v.w;
    }
    __shared__ float ss[256], sqq[256];
    ss[threadIdx.x] = s;
    sqq[threadIdx.x] = sq;
    __syncthreads();
    for (int st = 128; st > 0; st >>= 1) {
        if (threadIdx.x < st) {
            ss[threadIdx.x] += ss[threadIdx.x + st];
            sqq[threadIdx.x] += sqq[threadIdx.x + st];
        }
        __syncthreads();
    }
    if (threadIdx.x == 0) {
        float m = ss[0] / (float)N;
        mean[o] = m;
        var[o] = sqq[0] / (float)N - m * m;
    }
}

// ---------------------------------------------------------------------------
// BN apply + ReLU (float4); writes dst[b][c0+o][p] with channel-dim dstC.
// ---------------------------------------------------------------------------
__global__ void bnapply_k(const float* __restrict__ OUT,
                          const float* __restrict__ mean,
                          const float* __restrict__ var,
                          const float* __restrict__ gamma,
                          const float* __restrict__ beta,
                          float* __restrict__ dst, int Cout, int dstC, int c0) {
    int idx = blockIdx.x * blockDim.x + threadIdx.x;
    int N4 = N / 4;
    if (idx >= Cout * N4) return;
    int o = idx / N4;
    int n = (idx % N4) * 4;
    int b = n / P, p = n % P;
    float inv = rsqrtf(var[o] + BN_EPS);
    float g = gamma[o] * inv;
    float bt = beta[o] - mean[o] * g;
    float4 v = *(const float4*)&OUT[(size_t)o * N + n];
    v.x = fmaxf(fmaf(v.x, g, bt), 0.f);
    v.y = fmaxf(fmaf(v.y, g, bt), 0.f);
    v.z = fmaxf(fmaf(v.z, g, bt), 0.f);
    v.w = fmaxf(fmaf(v.w, g, bt), 0.f);
    *(float4*)&dst[((size_t)b * dstC + c0 + o) * P + p] = v;
}

// ---------------------------------------------------------------------------
// Host-side orchestration
// ---------------------------------------------------------------------------
static void deform_layer(const float* Xin, int Cin, int Cout, int kc, int pad,
                         const float* woff, const float* boff,
                         const float* wmain, const float* gamma,
                         const float* beta, float* dst, int dstC, int c0,
                         float* samp, float* off, float* outb, float* mean,
                         float* var) {
    int K = kc * kc * kc;
    int Kd = Cin * K;

    if (kc == 1) {
        gemv3_k<<<49, 256>>>(woff, boff, Xin, off, Cin);
    } else {
        int total = Kd * N;
        im2col_k<<<(total + 255) / 256, 256>>>(Xin, samp, Cin, kc, pad, total);
        dim3 g(98, (3 * K + 127) / 128);
        sgemm128_k<<<g, 256>>>(woff, samp, boff, off, 3 * K, Kd);
    }

    dim3 gs(98, K);
    dsample_k<<<gs, 128>>>(Xin, off, samp, Cin, kc, pad);

    if (Cout > 32) {
        dim3 g(98, (Cout + 127) / 128);
        sgemm128_k<<<g, 256>>>(wmain, samp, nullptr, outb, Cout, Kd);
    } else {
        gemv32_k<<<25, 256>>>(wmain, samp, outb, Kd);
    }

    bnstats_k<<<Cout, 256>>>(outb, mean, var);
    int tot4 = Cout * (N / 4);
    bnapply_k<<<(tot4 + 255) / 256, 256>>>(outb, mean, var, gamma, beta, dst,
                                           Cout, dstC, c0);
}

extern "C" void kernel_launch(void* const* d_in, const int* in_sizes, int n_in,
                              void* d_out, int out_size) {
    const float* x = (const float*)d_in[0];
    float* out = (float*)d_out;

    float *samp, *off, *outb, *t1, *t3, *xm, *mean, *var;
    cudaGetSymbolAddress((void**)&samp, g_samp);
    cudaGetSymbolAddress((void**)&off, g_off);
    cudaGetSymbolAddress((void**)&outb, g_outb);
    cudaGetSymbolAddress((void**)&t1, g_t1);
    cudaGetSymbolAddress((void**)&t3, g_t3);
    cudaGetSymbolAddress((void**)&xm, g_xm);
    cudaGetSymbolAddress((void**)&mean, g_mean);
    cudaGetSymbolAddress((void**)&var, g_var);

    auto L = [&](int i, int j) { return (const float*)d_in[1 + 5 * i + j]; };

    // branch0: x0 = deform(x, 832->256, k1) -> out channels [0,256)
    deform_layer(x, 832, 256, 1, 0, L(0, 0), L(0, 1), L(0, 2), L(0, 3), L(0, 4),
                 out, 832, 0, samp, off, outb, mean, var);

    // branch1: t1 = deform(x, 832->160, k1); x1 = deform(t1, 160->320, k3,p1)
    deform_layer(x, 832, 160, 1, 0, L(1, 0), L(1, 1), L(1, 2), L(1, 3), L(1, 4),
                 t1, 160, 0, samp, off, outb, mean, var);
    deform_layer(t1, 160, 320, 3, 1, L(2, 0), L(2, 1), L(2, 2), L(2, 3),
                 L(2, 4), out, 832, 256, samp, off, outb, mean, var);

    // branch2: t3 = deform(x, 832->32, k1); x2 = deform(t3, 32->128, k3,p1)
    deform_layer(x, 832, 32, 1, 0, L(3, 0), L(3, 1), L(3, 2), L(3, 3), L(3, 4),
                 t3, 32, 0, samp, off, outb, mean, var);
    deform_layer(t3, 32, 128, 3, 1, L(4, 0), L(4, 1), L(4, 2), L(4, 3),
                 L(4, 4), out, 832, 576, samp, off, outb, mean, var);

    // branch3: xm = maxpool3d(x); x3 = deform(xm, 832->128, k1)
    maxpool_k<<<(B * 832 * P + 255) / 256, 256>>>(x, xm, B * 832);
    deform_layer(xm, 832, 128, 1, 0, L(5, 0), L(5, 1), L(5, 2), L(5, 3),
                 L(5, 4), out, 832, 704, samp, off, outb, mean, var);
}